// round 13
// baseline (speedup 1.0000x reference)
#include <cuda_runtime.h>
#include <cuda_fp16.h>
#include <math.h>

#define B_SIZE    8192
#define K_FEATS   32
#define FT_OUT    512
#define BUCKETS   8
#define FT_VOCAB  40960
#define FFT_VOCAB 640

// Combined table quantized to int8 (biased-by-128 bytes) + per-row scale.
// comb[i][f] = ft_w[i][f] + fft_w[i%640][f]  ~=  (byte - 128) * g_scale[i]
__device__ unsigned char g_comb8[FT_VOCAB * FT_OUT];
__device__ float         g_scale[FT_VOCAB];

__device__ __forceinline__ int dp4a_us(unsigned int a, int b, int c) {
    int d;
    asm("dp4a.u32.s32 %0, %1, %2, %3;" : "=r"(d) : "r"(a), "r"(b), "r"(c));
    return d;
}

// ---------------------------------------------------------------------------
// Pass 1: quantize combined table. Warp-per-row, register-resident, at the
// DRAM floor (~15 us). Unchanged since R7.
// ---------------------------------------------------------------------------
__global__ __launch_bounds__(256)
void combine_q_kernel(const float4* __restrict__ ftw,
                      const float4* __restrict__ fftw) {
    const int warp = threadIdx.x >> 5;
    const int lane = threadIdx.x & 31;
    const int row  = blockIdx.x * 8 + warp;

    const float4* fa = ftw  + (size_t)row * 128;
    const float4* fb = fftw + (size_t)(row % FFT_VOCAB) * 128;

    float4 c[4];
    #pragma unroll
    for (int i = 0; i < 4; ++i) {
        float4 a = __ldcs(fa + i * 32 + lane);
        float4 b = __ldg(fb + i * 32 + lane);
        c[i].x = a.x + b.x; c[i].y = a.y + b.y;
        c[i].z = a.z + b.z; c[i].w = a.w + b.w;
    }

    float m = 0.f;
    #pragma unroll
    for (int i = 0; i < 4; ++i)
        m = fmaxf(m, fmaxf(fmaxf(fabsf(c[i].x), fabsf(c[i].y)),
                           fmaxf(fabsf(c[i].z), fabsf(c[i].w))));
    #pragma unroll
    for (int o = 16; o > 0; o >>= 1)
        m = fmaxf(m, __shfl_xor_sync(0xffffffffu, m, o));
    m = fmaxf(m, 1e-20f);

    const float inv = 127.0f / m;
    uchar4* dst = reinterpret_cast<uchar4*>(g_comb8) + (size_t)row * 128;
    #pragma unroll
    for (int i = 0; i < 4; ++i) {
        uchar4 pk;
        pk.x = (unsigned char)(__float2int_rn(c[i].x * inv) + 128);
        pk.y = (unsigned char)(__float2int_rn(c[i].y * inv) + 128);
        pk.z = (unsigned char)(__float2int_rn(c[i].z * inv) + 128);
        pk.w = (unsigned char)(__float2int_rn(c[i].w * inv) + 128);
        dst[i * 32 + lane] = pk;
    }
    if (lane == 0) g_scale[row] = m * (1.0f / 127.0f);
}

// ---------------------------------------------------------------------------
// Pass 2: one block per batch row, 128 threads (R8 layout).
//   warps 0-1 (t < 64):  stm half,  thread owns feats [8*col, 8*col+8)
//   warps 2-3 (t >= 64): nstm half
// Masked-DP4A decode: stage-1 PRMT only ({r0f,r1f,r0f',r1f'} pairs) and
// zero-masked V words ({V0,V1,0,0} / {0,0,V0,V1} / ...) prebuilt in shared.
// Per chunk of 4 k: 2 LDS.128 + 4 LDG.64 + 8 PRMT + 16 DP4A.
// Integer math identical to R8 (each product appears exactly once).
// ---------------------------------------------------------------------------
__global__ __launch_bounds__(128)
void nnue_kernel(const float*  __restrict__ values,
                 const int*    __restrict__ stm_idx,
                 const int*    __restrict__ nstm_idx,
                 const int*    __restrict__ buckets,
                 const float*  __restrict__ ft_b,
                 const float*  __restrict__ fft_b,
                 const float*  __restrict__ out_w,
                 const float*  __restrict__ out_b,
                 float*        __restrict__ out) {
    const int b = blockIdx.x;
    const int t = threadIdx.x;
    const int half_sel = t >> 6;
    const int col      = t & 63;

    __shared__ int   offs[2][K_FEATS];
    __shared__ int   sVW[2][K_FEATS];   // masked V words: [side][chunk*4 + j]
    __shared__ float sSq[2];
    __shared__ int   sSumV[2];
    __shared__ float red[4];

    {
        const int wid  = t >> 5;           // warp 0 -> stm, warp 2 -> nstm
        const int lane = t & 31;
        if ((wid & 1) == 0) {
            const int side = wid >> 1;
            const int* idxp = side ? nstm_idx : stm_idx;
            const int idx = idxp[b * K_FEATS + lane];
            offs[side][lane] = idx * FT_OUT;
            float vs = values[b * K_FEATS + lane] * g_scale[idx];

            // warp absmax -> per-side scale
            float m = fabsf(vs);
            #pragma unroll
            for (int o = 16; o > 0; o >>= 1)
                m = fmaxf(m, __shfl_xor_sync(0xffffffffu, m, o));
            m = fmaxf(m, 1e-30f);
            float Sq  = m * (1.0f / 127.0f);
            float inv = 127.0f / m;

            int V = __float2int_rn(vs * inv);         // in [-127,127]

            int sv = V;
            #pragma unroll
            for (int o = 16; o > 0; o >>= 1)
                sv += __shfl_xor_sync(0xffffffffu, sv, o);
            if (lane == 0) { sSq[side] = Sq; sSumV[side] = sv; }

            // Build masked V-words. lane encodes (chunk c = lane>>2, j = lane&3):
            //   j=0: {V(4c),V(4c+1),0,0}     j=1: {0,0,V(4c),V(4c+1)}
            //   j=2: {V(4c+2),V(4c+3),0,0}   j=3: {0,0,V(4c+2),V(4c+3)}
            const int c4 = (lane >> 2) << 2;
            const int j  = lane & 3;
            int Va = __shfl_sync(0xffffffffu, V, c4 + ((j >> 1) << 1));
            int Vb = __shfl_sync(0xffffffffu, V, c4 + ((j >> 1) << 1) + 1);
            unsigned lo = (Va & 0xff) | ((Vb & 0xff) << 8);
            sVW[side][lane] = (j & 1) ? (int)(lo << 16) : (int)lo;
        }
    }
    __syncthreads();

    const char* base = reinterpret_cast<const char*>(g_comb8) + col * 8;
    const int*  offp = offs[half_sel];
    const int*  vwp  = sVW[half_sel];

    int acc[8];
    #pragma unroll
    for (int f = 0; f < 8; ++f) acc[f] = 0;

    #pragma unroll
    for (int c = 0; c < 8; ++c) {                    // 8 chunks of 4 k-values
        int4 o4 = *reinterpret_cast<const int4*>(offp + c * 4);
        int4 vw = *reinterpret_cast<const int4*>(vwp + c * 4);
        uint2 u0 = *reinterpret_cast<const uint2*>(base + o4.x);
        uint2 u1 = *reinterpret_cast<const uint2*>(base + o4.y);
        uint2 u2 = *reinterpret_cast<const uint2*>(base + o4.z);
        uint2 u3 = *reinterpret_cast<const uint2*>(base + o4.w);

        // feats f0..f3 (low words): stage-1 pairs only
        unsigned ta = __byte_perm(u0.x, u1.x, 0x5140); // {r0f0,r1f0,r0f1,r1f1}
        unsigned tb = __byte_perm(u2.x, u3.x, 0x5140); // {r2f0,r3f0,r2f1,r3f1}
        unsigned tc = __byte_perm(u0.x, u1.x, 0x7362); // {r0f2,r1f2,r0f3,r1f3}
        unsigned td = __byte_perm(u2.x, u3.x, 0x7362); // {r2f2,r3f2,r2f3,r3f3}
        acc[0] = dp4a_us(ta, vw.x, acc[0]);   // V0,V1 on bytes 0,1
        acc[0] = dp4a_us(tb, vw.z, acc[0]);   // V2,V3 on bytes 0,1
        acc[1] = dp4a_us(ta, vw.y, acc[1]);   // V0,V1 on bytes 2,3
        acc[1] = dp4a_us(tb, vw.w, acc[1]);
        acc[2] = dp4a_us(tc, vw.x, acc[2]);
        acc[2] = dp4a_us(td, vw.z, acc[2]);
        acc[3] = dp4a_us(tc, vw.y, acc[3]);
        acc[3] = dp4a_us(td, vw.w, acc[3]);

        // feats f4..f7 (high words)
        ta = __byte_perm(u0.y, u1.y, 0x5140);
        tb = __byte_perm(u2.y, u3.y, 0x5140);
        tc = __byte_perm(u0.y, u1.y, 0x7362);
        td = __byte_perm(u2.y, u3.y, 0x7362);
        acc[4] = dp4a_us(ta, vw.x, acc[4]);
        acc[4] = dp4a_us(tb, vw.z, acc[4]);
        acc[5] = dp4a_us(ta, vw.y, acc[5]);
        acc[5] = dp4a_us(tb, vw.w, acc[5]);
        acc[6] = dp4a_us(tc, vw.x, acc[6]);
        acc[6] = dp4a_us(td, vw.z, acc[6]);
        acc[7] = dp4a_us(tc, vw.y, acc[7]);
        acc[7] = dp4a_us(td, vw.w, acc[7]);
    }

    // Undo +128 byte bias exactly, scale, add biases, clip.
    const float Sq   = sSq[half_sel];
    const int   corr = 128 * sSumV[half_sel];

    const float4* bb4 = reinterpret_cast<const float4*>(ft_b)  + col * 2;
    const float4* fb4 = reinterpret_cast<const float4*>(fft_b) + col * 2;
    float4 b0 = bb4[0], b1 = bb4[1], f0 = fb4[0], f1 = fb4[1];
    float bias[8] = { b0.x + f0.x, b0.y + f0.y, b0.z + f0.z, b0.w + f0.w,
                      b1.x + f1.x, b1.y + f1.y, b1.z + f1.z, b1.w + f1.w };

    float h[8];
    #pragma unroll
    for (int f = 0; f < 8; ++f) {
        h[f] = (float)(acc[f] - corr) * Sq + bias[f];
        h[f] = fminf(fmaxf(h[f], 0.f), 1.f);
    }

    // dot with the selected bucket row of out_w [BUCKETS, 2*FT_OUT]
    const int bk = buckets[b];
    const float4* wrow = reinterpret_cast<const float4*>(
        out_w + bk * (2 * FT_OUT) + half_sel * FT_OUT) + col * 2;
    float4 w0 = wrow[0], w1 = wrow[1];

    float local = h[0] * w0.x + h[1] * w0.y + h[2] * w0.z + h[3] * w0.w
                + h[4] * w1.x + h[5] * w1.y + h[6] * w1.z + h[7] * w1.w;

    #pragma unroll
    for (int o = 16; o > 0; o >>= 1)
        local += __shfl_down_sync(0xffffffffu, local, o);
    if ((t & 31) == 0) red[t >> 5] = local;
    __syncthreads();
    if (t == 0) {
        float s = red[0] + red[1] + red[2] + red[3] + out_b[bk];
        out[b] = 1.0f / (1.0f + expf(-s));
    }
}

extern "C" void kernel_launch(void* const* d_in, const int* in_sizes, int n_in,
                              void* d_out, int out_size) {
    const float* values   = (const float*)d_in[0];
    const int*   stm_idx  = (const int*)  d_in[1];
    const int*   nstm_idx = (const int*)  d_in[2];
    const int*   buckets  = (const int*)  d_in[3];
    const float* ft_w     = (const float*)d_in[4];
    const float* ft_b     = (const float*)d_in[5];
    const float* fft_w    = (const float*)d_in[6];
    const float* fft_b    = (const float*)d_in[7];
    const float* out_w    = (const float*)d_in[8];
    const float* out_b    = (const float*)d_in[9];
    float* out = (float*)d_out;

    (void)in_sizes; (void)n_in; (void)out_size;

    combine_q_kernel<<<FT_VOCAB / 8, 256>>>(
        reinterpret_cast<const float4*>(ft_w),
        reinterpret_cast<const float4*>(fft_w));

    nnue_kernel<<<B_SIZE, 128>>>(values, stm_idx, nstm_idx, buckets,
                                 ft_b, fft_b, out_w, out_b, out);
}